// round 7
// baseline (speedup 1.0000x reference)
#include <cuda_runtime.h>
#include <cuda_fp16.h>
#include <cstdint>
#include <math.h>

// ---------------------------------------------------------------------------
// Problem constants
// ---------------------------------------------------------------------------
#define Nn 16
#define Hh 112
#define Wd 112
#define Cc 128
#define Ho 110
#define Wo 110
#define Co 256
#define KK 1152                 // 3*3*128
#define MM (Nn*Ho*Wo)           // 193600
#define PIX (Nn*Hh*Wd)          // 200704
#define TT 48400                // winograd tiles: 16*55*55
#define THW 3025                // 55*55
#define TPAD 48416              // 1513*32
#define FIXCAP (1u << 21)
#define TAU 1e-4f               // |y| threshold for exact fp32 recompute

// ---------------------------------------------------------------------------
// Scratch (device globals; no allocations allowed)
// ---------------------------------------------------------------------------
__device__ float g_s[PIX];
__device__ float g_xni[MM];
__device__ float g_ws[Co];
__device__ float g_ae[Co];
__device__ __half g_At[16ull * TPAD * Cc];   // transformed input, [ij][t][c]
__device__ __half g_Bt[16 * Co * Cc];        // transformed weights, [ij][co][c]
__device__ float  g_WT[Co * KK];             // W fp32 [co][k] (fixup)
__device__ uint32_t g_fix_list[FIXCAP];
__device__ uint32_t g_fix_cnt;

__constant__ float c_a0[4] = {1.f, 1.f,  1.f,  0.f};   // A^T row 0
__constant__ float c_a1[4] = {0.f, 1.f, -1.f, -1.f};   // A^T row 1

// ---------------------------------------------------------------------------
// Helpers
// ---------------------------------------------------------------------------
__device__ __forceinline__ uint32_t smem_u32(const void* p) {
    uint32_t a;
    asm("{ .reg .u64 t; cvta.to.shared.u64 t, %1; cvt.u32.u64 %0, t; }"
        : "=r"(a) : "l"(p));
    return a;
}
#define CP16(dst, src) \
    asm volatile("cp.async.cg.shared.global [%0], [%1], 16;" \
                 :: "r"(dst), "l"(src) : "memory")

#define MMA_F16(cc, a, b)                                                     \
    asm volatile("mma.sync.aligned.m16n8k16.row.col.f32.f16.f16.f32 "        \
        "{%0,%1,%2,%3}, {%4,%5,%6,%7}, {%8,%9}, {%0,%1,%2,%3};"              \
        : "+f"((cc)[0]), "+f"((cc)[1]), "+f"((cc)[2]), "+f"((cc)[3])         \
        : "r"((a)[0]), "r"((a)[1]), "r"((a)[2]), "r"((a)[3]),                \
          "r"((b)[0]), "r"((b)[1]))

#define LDSM_X4(r0, r1, r2, r3, addr)                                        \
    asm volatile("ldmatrix.sync.aligned.m8n8.x4.shared.b16 {%0,%1,%2,%3}, [%4];" \
        : "=r"(r0), "=r"(r1), "=r"(r2), "=r"(r3) : "r"(addr))

// ---------------------------------------------------------------------------
// Kernel 1: weight norms / exponents; resets fixup counter
// ---------------------------------------------------------------------------
__global__ void prep_w_kernel(const float* __restrict__ W,
                              const float* __restrict__ p,
                              const float* __restrict__ q) {
    __shared__ float red[256];
    int c = blockIdx.x, t = threadIdx.x;
    if (blockIdx.x == 0 && t == 0) g_fix_cnt = 0;
    float s = 0.0f;
    for (int k = t; k < KK; k += 256) {
        float w = W[k * Co + c];
        s = fmaf(w, w, s);
    }
    red[t] = s; __syncthreads();
    for (int o = 128; o > 0; o >>= 1) {
        if (t < o) red[t] += red[t + o];
        __syncthreads();
    }
    if (t == 0) {
        float qq = q[0] * q[0] * 0.1f;
        g_ws[c] = 1.0f / (sqrtf(red[0]) + qq);
        g_ae[c] = p[c] * p[c] * 0.01f;
    }
}

// ---------------------------------------------------------------------------
// Kernel 1b: weight transform G g G^T -> g_Bt[ij][co][c] fp16, plus g_WT fp32.
// grid 129: blocks 0..127 = channel c; block 128 zeroes the A-plane tail pad.
// ---------------------------------------------------------------------------
__global__ void wt_transform_kernel(const float* __restrict__ W) {
    if (blockIdx.x == 128) {
        for (int i = threadIdx.x; i < 16 * 16 * 128; i += 256) {
            int ij = i >> 11;
            int rem = i & 2047;
            int rowp = rem >> 7;
            int c = rem & 127;
            g_At[((size_t)ij * TPAD + TT + rowp) * Cc + c] = __float2half(0.0f);
        }
        return;
    }
    int c  = blockIdx.x;
    int co = threadIdx.x;
    float g[3][3];
    #pragma unroll
    for (int r = 0; r < 3; ++r)
        #pragma unroll
        for (int s = 0; s < 3; ++s) {
            float w = W[((r * 3 + s) * Cc + c) * Co + co];
            g[r][s] = w;
            g_WT[(size_t)co * KK + (r * 3 + s) * Cc + c] = w;
        }
    // u = G g  (4x3)
    float u[4][3];
    #pragma unroll
    for (int s = 0; s < 3; ++s) {
        u[0][s] = g[0][s];
        u[1][s] = 0.5f * (g[0][s] + g[1][s] + g[2][s]);
        u[2][s] = 0.5f * (g[0][s] - g[1][s] + g[2][s]);
        u[3][s] = g[2][s];
    }
    // v = u G^T (4x4)
    #pragma unroll
    for (int i = 0; i < 4; ++i) {
        float v0 = u[i][0];
        float v1 = 0.5f * (u[i][0] + u[i][1] + u[i][2]);
        float v2 = 0.5f * (u[i][0] - u[i][1] + u[i][2]);
        float v3 = u[i][2];
        g_Bt[((i * 4 + 0) * Co + co) * Cc + c] = __float2half_rn(v0);
        g_Bt[((i * 4 + 1) * Co + co) * Cc + c] = __float2half_rn(v1);
        g_Bt[((i * 4 + 2) * Co + co) * Cc + c] = __float2half_rn(v2);
        g_Bt[((i * 4 + 3) * Co + co) * Cc + c] = __float2half_rn(v3);
    }
}

// ---------------------------------------------------------------------------
// Kernel 2: per-input-pixel sum of x^2 (one warp per pixel)
// ---------------------------------------------------------------------------
__global__ void sumsq_kernel(const float* __restrict__ x) {
    int pix  = blockIdx.x * 8 + (threadIdx.x >> 5);
    int lane = threadIdx.x & 31;
    const float4* xp = reinterpret_cast<const float4*>(x + (size_t)pix * Cc);
    float4 v = xp[lane];
    float s = v.x * v.x + v.y * v.y + v.z * v.z + v.w * v.w;
    #pragma unroll
    for (int o = 16; o > 0; o >>= 1) s += __shfl_xor_sync(0xffffffffu, s, o);
    if (lane == 0) g_s[pix] = s;
}

// ---------------------------------------------------------------------------
// Kernel 3: 3x3 window sum -> inverse patch norm
// ---------------------------------------------------------------------------
__global__ void xnorm_kernel(const float* __restrict__ q) {
    int idx = blockIdx.x * 256 + threadIdx.x;
    if (idx >= MM) return;
    int n = idx / (Ho * Wo);
    int r = idx % (Ho * Wo);
    int h = r / Wo;
    int w = r % Wo;
    const float* sp = g_s + ((size_t)n * Hh + h) * Wd + w;
    float sum = 0.0f;
    #pragma unroll
    for (int ky = 0; ky < 3; ++ky)
        sum += sp[ky * Wd] + sp[ky * Wd + 1] + sp[ky * Wd + 2];
    float qq = q[0] * q[0] * 0.1f;
    g_xni[idx] = 1.0f / (sqrtf(sum) + qq);
}

// ---------------------------------------------------------------------------
// Kernel 4: input transform B^T d B -> g_At[ij][t][c] fp16.
// Thread = (tile t, channel c).
// ---------------------------------------------------------------------------
__global__ void in_transform_kernel(const float* __restrict__ x) {
    int idx = blockIdx.x * 256 + threadIdx.x;    // TT*128 exact
    int t = idx >> 7;
    int c = idx & 127;
    int n  = t / THW;
    int rr = t % THW;
    int ty = rr / 55;
    int tx = rr % 55;
    const float* xp = x + (((size_t)n * Hh + 2 * ty) * Wd + 2 * tx) * Cc + c;

    float d[4][4];
    #pragma unroll
    for (int r = 0; r < 4; ++r)
        #pragma unroll
        for (int s = 0; s < 4; ++s)
            d[r][s] = xp[(r * Wd + s) * Cc];

    // u = B^T d  (rows)
    float u[4][4];
    #pragma unroll
    for (int s = 0; s < 4; ++s) {
        u[0][s] = d[0][s] - d[2][s];
        u[1][s] = d[1][s] + d[2][s];
        u[2][s] = d[2][s] - d[1][s];
        u[3][s] = d[1][s] - d[3][s];
    }
    // v = u B (cols)
    #pragma unroll
    for (int i = 0; i < 4; ++i) {
        float v0 = u[i][0] - u[i][2];
        float v1 = u[i][1] + u[i][2];
        float v2 = u[i][2] - u[i][1];
        float v3 = u[i][1] - u[i][3];
        g_At[((size_t)(i * 4 + 0) * TPAD + t) * Cc + c] = __float2half_rn(v0);
        g_At[((size_t)(i * 4 + 1) * TPAD + t) * Cc + c] = __float2half_rn(v1);
        g_At[((size_t)(i * 4 + 2) * TPAD + t) * Cc + c] = __float2half_rn(v2);
        g_At[((size_t)(i * 4 + 3) * TPAD + t) * Cc + c] = __float2half_rn(v3);
    }
}

// ---------------------------------------------------------------------------
// Kernel 5: Winograd GEMM. CTA = 32 tiles x 256 cout, 512 threads (16 warps,
// each 32t x 16co). Loops 16 ij phases (32 K-substages of 64), folds each
// phase's G into 4 output accumulators (A^T . A coefficients), then fused
// cosine-power epilogue + candidate flagging.
// ---------------------------------------------------------------------------
#define NSTG 32
#define RG_B 4096
#define STG  36864              // A 4KB + B 32KB
#define SMEM_DYN (3 * STG)      // 110592
#define LISTCAP 8192

extern __shared__ char dsm[];

__global__ void __launch_bounds__(512, 1)
conv_wino_kernel(const float* __restrict__ bias, float* __restrict__ out) {
    __shared__ float s_ws[Co], s_ae[Co], s_bi[Co];
    __shared__ uint32_t s_cnt, s_base;

    const uint32_t sbase = smem_u32(dsm);
    const int t    = threadIdx.x;
    const int w    = t >> 5;
    const int lane = t & 31;
    const int gid  = lane >> 2;
    const int tig  = lane & 3;
    const int t0   = blockIdx.x * 32;
    const int wno  = w * 16;

    if (t < Co) {
        s_ws[t] = g_ws[t];
        s_ae[t] = g_ae[t];
        s_bi[t] = bias[t];
    }
    if (t == 0) s_cnt = 0;
    __syncthreads();

    // ldmatrix invariants
    const uint32_t sw    = lane & 7;
    const uint32_t aRow0 = (uint32_t)(lane & 15) * 128u;
    const uint32_t aRow1 = aRow0 + 16u * 128u;
    const uint32_t aCsel = (lane >> 4);
    const uint32_t bRow  = (uint32_t)(wno + ((lane >> 4) << 3) + (lane & 7)) * 128u;
    const uint32_t bCsel = (lane >> 3) & 1;

    float O0[16], O1[16], O2[16], O3[16], G[16];
    #pragma unroll
    for (int i = 0; i < 16; ++i) { O0[i]=0.f; O1[i]=0.f; O2[i]=0.f; O3[i]=0.f; G[i]=0.f; }

    #define STAGE_CP(s) do {                                                  \
        uint32_t bb = sbase + (uint32_t)((s) % 3) * STG;                      \
        int ij   = (s) >> 1;                                                  \
        int half = ((s) & 1) * 64;                                            \
        if (t < 256) {                                                        \
            int row = t >> 3, ch = t & 7;                                     \
            const __half* src = g_At + ((size_t)ij * TPAD + (size_t)(t0 + row)) * Cc + half + ch * 8; \
            uint32_t dof = (uint32_t)row * 128u + (uint32_t)((ch ^ (row & 7)) << 4); \
            CP16(bb + dof, src);                                              \
        }                                                                     \
        {                                                                     \
            int row = t >> 1;                                                 \
            int gg  = (t & 1) * 4;                                            \
            const __half* srcb = g_Bt + ((size_t)ij * Co + row) * Cc + half;  \
            _Pragma("unroll")                                                 \
            for (int i2 = 0; i2 < 4; ++i2) {                                  \
                int ch = gg + i2;                                             \
                uint32_t dof = (uint32_t)row * 128u + (uint32_t)((ch ^ (row & 7)) << 4); \
                CP16(bb + RG_B + dof, srcb + ch * 8);                         \
            }                                                                 \
        }                                                                     \
        asm volatile("cp.async.commit_group;" ::: "memory");                  \
    } while (0)

    STAGE_CP(0);
    STAGE_CP(1);

    for (int s = 0; s < NSTG; ++s) {
        if (s + 1 < NSTG)
            asm volatile("cp.async.wait_group 1;" ::: "memory");
        else
            asm volatile("cp.async.wait_group 0;" ::: "memory");
        __syncthreads();
        if (s + 2 < NSTG) STAGE_CP(s + 2);

        const uint32_t aB = sbase + (uint32_t)(s % 3) * STG;
        const uint32_t bB = aB + RG_B;

        #pragma unroll
        for (int ks = 0; ks < 4; ++ks) {
            const uint32_t offA = (((uint32_t)(2 * ks) + aCsel) ^ sw) << 4;
            const uint32_t offB = (((uint32_t)(2 * ks) + bCsel) ^ sw) << 4;
            uint32_t ah[2][4], bv[2][2];
            LDSM_X4(ah[0][0], ah[0][1], ah[0][2], ah[0][3], aB + aRow0 + offA);
            LDSM_X4(ah[1][0], ah[1][1], ah[1][2], ah[1][3], aB + aRow1 + offA);
            LDSM_X4(bv[0][0], bv[0][1], bv[1][0], bv[1][1], bB + bRow + offB);
            MMA_F16(G + 0,  ah[0], bv[0]);
            MMA_F16(G + 4,  ah[0], bv[1]);
            MMA_F16(G + 8,  ah[1], bv[0]);
            MMA_F16(G + 12, ah[1], bv[1]);
        }

        if (s & 1) {   // end of an ij phase: fold G into O with A^T coeffs
            int ij = s >> 1;
            int ii = ij >> 2, jj = ij & 3;
            float cy0 = c_a0[ii], cy1 = c_a1[ii];
            float cx0 = c_a0[jj], cx1 = c_a1[jj];
            float c00 = cy0 * cx0, c01 = cy0 * cx1;
            float c10 = cy1 * cx0, c11 = cy1 * cx1;
            #pragma unroll
            for (int r = 0; r < 16; ++r) {
                float gv = G[r];
                O0[r] = fmaf(c00, gv, O0[r]);
                O1[r] = fmaf(c01, gv, O1[r]);
                O2[r] = fmaf(c10, gv, O2[r]);
                O3[r] = fmaf(c11, gv, O3[r]);
                G[r] = 0.0f;
            }
        }
        __syncthreads();
    }

    // ---- fused epilogue: inverse-transform accumulators -> 4 output pixels ----
    uint32_t* s_list = (uint32_t*)dsm;

    #pragma unroll
    for (int mi = 0; mi < 2; ++mi) {
        #pragma unroll
        for (int e2 = 0; e2 < 2; ++e2) {
            int trow = t0 + mi * 16 + gid + 8 * e2;
            if (trow >= TT) continue;
            int n  = trow / THW;
            int rr = trow % THW;
            int ty = rr / 55;
            int tx = rr % 55;
            int mbase = n * (Ho * Wo) + 2 * ty * Wo + 2 * tx;
            #pragma unroll
            for (int y = 0; y < 2; ++y) {
                #pragma unroll
                for (int xx = 0; xx < 2; ++xx) {
                    int m = mbase + y * Wo + xx;
                    float xn = g_xni[m];
                    const float* Oa = (y == 0) ? (xx == 0 ? O0 : O1)
                                               : (xx == 0 ? O2 : O3);
                    #pragma unroll
                    for (int ni = 0; ni < 2; ++ni) {
                        int co = wno + ni * 8 + 2 * tig;
                        int ri = mi * 8 + ni * 4 + 2 * e2;
                        float f0 = Oa[ri]     + s_bi[co];
                        float f1 = Oa[ri + 1] + s_bi[co + 1];
                        float y0 = f0 * xn * s_ws[co];
                        float y1 = f1 * xn * s_ws[co + 1];
                        if (fabsf(y0) < TAU) {
                            uint32_t i = atomicAdd(&s_cnt, 1u);
                            if (i < LISTCAP) s_list[i] = ((uint32_t)m << 8) | (uint32_t)co;
                        }
                        if (fabsf(y1) < TAU) {
                            uint32_t i = atomicAdd(&s_cnt, 1u);
                            if (i < LISTCAP) s_list[i] = ((uint32_t)m << 8) | (uint32_t)(co + 1);
                        }
                        float a0 = fabsf(y0) + 1e-12f;
                        float a1 = fabsf(y1) + 1e-12f;
                        float o0 = copysignf(__expf(s_ae[co]     * __logf(a0)), f0);
                        float o1 = copysignf(__expf(s_ae[co + 1] * __logf(a1)), f1);
                        *reinterpret_cast<float2*>(out + (size_t)m * Co + co) =
                            make_float2(o0, o1);
                    }
                }
            }
        }
    }

    __syncthreads();
    if (t == 0) {
        uint32_t cc = s_cnt < LISTCAP ? s_cnt : LISTCAP;
        s_cnt = cc;
        s_base = atomicAdd(&g_fix_cnt, cc);
    }
    __syncthreads();
    for (uint32_t i = t; i < s_cnt; i += 512) {
        uint32_t gidx = s_base + i;
        if (gidx < FIXCAP) g_fix_list[gidx] = s_list[i];
    }
    #undef STAGE_CP
}

// ---------------------------------------------------------------------------
// Kernel 6: exact fp32 recompute of flagged elements (warp per candidate)
// ---------------------------------------------------------------------------
__global__ void fixup_kernel(const float* __restrict__ x,
                             const float* __restrict__ bias,
                             float* __restrict__ out) {
    uint32_t total = g_fix_cnt;
    if (total > FIXCAP) total = FIXCAP;
    uint32_t wid   = (blockIdx.x * blockDim.x + threadIdx.x) >> 5;
    uint32_t nwarp = (gridDim.x * blockDim.x) >> 5;
    int lane = threadIdx.x & 31;

    for (uint32_t e = wid; e < total; e += nwarp) {
        uint32_t enc = g_fix_list[e];
        int m  = enc >> 8;
        int co = enc & 255;
        int n = m / (Ho * Wo);
        int r = m % (Ho * Wo);
        int h = r / Wo;
        int ww = r % Wo;
        int base = ((n * Hh + h) * Wd + ww) * Cc;

        float sum = 0.0f;
        #pragma unroll
        for (int g = 0; g < 9; ++g) {
            int ky = g / 3, kx = g - ky * 3;
            const float* xp = x + base + (ky * Wd + kx) * Cc;
            const float* wp = g_WT + (size_t)co * KK + g * Cc;
            #pragma unroll
            for (int ci = 0; ci < 4; ++ci) {
                int cch = ci * 32 + lane;
                sum = fmaf(xp[cch], wp[cch], sum);
            }
        }
        #pragma unroll
        for (int o = 16; o > 0; o >>= 1)
            sum += __shfl_xor_sync(0xffffffffu, sum, o);

        if (lane == 0) {
            float f  = sum + bias[co];
            float y  = f * g_xni[m] * g_ws[co];
            float ay = fabsf(y) + 1e-12f;
            float rr = __expf(g_ae[co] * __logf(ay));
            out[(size_t)m * Co + co] = copysignf(rr, f);
        }
    }
}

// ---------------------------------------------------------------------------
extern "C" void kernel_launch(void* const* d_in, const int* in_sizes, int n_in,
                              void* d_out, int out_size) {
    const float* x = (const float*)d_in[0];
    const float* W = (const float*)d_in[1];
    const float* b = (const float*)d_in[2];
    const float* p = (const float*)d_in[3];
    const float* q = (const float*)d_in[4];
    float* out = (float*)d_out;

    prep_w_kernel<<<Co, 256>>>(W, p, q);
    wt_transform_kernel<<<129, 256>>>(W);
    sumsq_kernel<<<PIX / 8, 256>>>(x);
    xnorm_kernel<<<(MM + 255) / 256, 256>>>(q);
    in_transform_kernel<<<(TT * 128) / 256, 256>>>(x);

    static bool attr_set = false;
    if (!attr_set) {
        cudaFuncSetAttribute(conv_wino_kernel,
                             cudaFuncAttributeMaxDynamicSharedMemorySize, SMEM_DYN);
        attr_set = true;
    }
    conv_wino_kernel<<<TPAD / 32, 512, SMEM_DYN>>>(b, out);

    fixup_kernel<<<512, 256>>>(x, b, out);
}

// round 8
// speedup vs baseline: 1.4111x; 1.4111x over previous
#include <cuda_runtime.h>
#include <cuda_fp16.h>
#include <cstdint>
#include <math.h>

// ---------------------------------------------------------------------------
// Problem constants
// ---------------------------------------------------------------------------
#define Nn 16
#define Hh 112
#define Wd 112
#define Cc 128
#define Ho 110
#define Wo 110
#define Co 256
#define KK 1152                 // 3*3*128
#define MM (Nn*Ho*Wo)           // 193600
#define PIX (Nn*Hh*Wd)          // 200704
#define TT 48400                // winograd tiles: 16*55*55
#define THW 3025                // 55*55
#define NMB 1513                // M-blocks of 32 tiles (48416 padded)
#define FIXCAP (1u << 21)
#define TAU 1e-4f               // |y| threshold for exact fp32 recompute

// ---------------------------------------------------------------------------
// Scratch (device globals; no allocations allowed)
// ---------------------------------------------------------------------------
__device__ float g_s[PIX];
__device__ float g_xni[MM];
__device__ float g_ws[Co];
__device__ float g_ae[Co];
// A image: [stage s=ij*2+half][mblock b][4096B swizzled 32rows x 128B]
__device__ unsigned char g_AtI[32ull * NMB * 4096];
// B image: [stage s][32768B swizzled 256rows x 128B]
__device__ unsigned char g_BtI[32ull * 32768];
__device__ float  g_WT[Co * KK];             // W fp32 [co][k] (fixup)
__device__ uint32_t g_fix_list[FIXCAP];
__device__ uint32_t g_fix_cnt;

__constant__ float c_a0[4] = {1.f, 1.f,  1.f,  0.f};   // A^T row 0
__constant__ float c_a1[4] = {0.f, 1.f, -1.f, -1.f};   // A^T row 1

// ---------------------------------------------------------------------------
// Helpers
// ---------------------------------------------------------------------------
__device__ __forceinline__ uint32_t smem_u32(const void* p) {
    uint32_t a;
    asm("{ .reg .u64 t; cvta.to.shared.u64 t, %1; cvt.u32.u64 %0, t; }"
        : "=r"(a) : "l"(p));
    return a;
}

#define MMA_F16(cc, a, b)                                                     \
    asm volatile("mma.sync.aligned.m16n8k16.row.col.f32.f16.f16.f32 "        \
        "{%0,%1,%2,%3}, {%4,%5,%6,%7}, {%8,%9}, {%0,%1,%2,%3};"              \
        : "+f"((cc)[0]), "+f"((cc)[1]), "+f"((cc)[2]), "+f"((cc)[3])         \
        : "r"((a)[0]), "r"((a)[1]), "r"((a)[2]), "r"((a)[3]),                \
          "r"((b)[0]), "r"((b)[1]))

#define LDSM_X4(r0, r1, r2, r3, addr)                                        \
    asm volatile("ldmatrix.sync.aligned.m8n8.x4.shared.b16 {%0,%1,%2,%3}, [%4];" \
        : "=r"(r0), "=r"(r1), "=r"(r2), "=r"(r3) : "r"(addr))

#define BULK_CP(dst, src, bytes, mbar)                                        \
    asm volatile("cp.async.bulk.shared::cta.global.mbarrier::complete_tx::bytes " \
        "[%0], [%1], %2, [%3];"                                               \
        :: "r"(dst), "l"(src), "r"(bytes), "r"(mbar) : "memory")

#define MBARRIER_INIT(mbar, cnt) \
    asm volatile("mbarrier.init.shared.b64 [%0], %1;" \
                 :: "r"((uint32_t)(mbar)), "r"((uint32_t)(cnt)) : "memory")
#define MBARRIER_EXPECT_TX(mbar, bytes) \
    asm volatile("mbarrier.arrive.expect_tx.shared.b64 _, [%0], %1;" \
                 :: "r"((uint32_t)(mbar)), "r"((uint32_t)(bytes)) : "memory")
#define FENCE_ASYNC() asm volatile("fence.proxy.async.shared::cta;" ::: "memory")

#define MBARRIER_WAIT_PARITY(mbar_addr, phase_parity) do {                       \
    uint32_t _mbar = (uint32_t)(mbar_addr);                                      \
    uint32_t _parity = (uint32_t)(phase_parity);                                 \
    uint32_t _done;                                                              \
    asm volatile("{\n\t.reg .pred p;\n\t"                                        \
        "mbarrier.try_wait.parity.acquire.cta.shared::cta.b64 p, [%1], %2;\n\t"  \
        "selp.b32 %0, 1, 0, p;\n\t}"                                             \
        : "=r"(_done) : "r"(_mbar), "r"(_parity) : "memory");                    \
    if (!_done) {                                                                \
        asm volatile("{\n\t.reg .pred P1;\n\t"                                   \
            "WAIT_LOOP_%=:\n\t"                                                  \
            "mbarrier.try_wait.parity.acquire.cta.shared::cta.b64 P1, [%0], %1, 0x989680;\n\t" \
            "@P1 bra.uni WAIT_DONE_%=;\n\t"                                      \
            "bra.uni WAIT_LOOP_%=;\n\t"                                          \
            "WAIT_DONE_%=:\n\t}"                                                 \
            :: "r"(_mbar), "r"(_parity) : "memory");                             \
    }                                                                            \
} while (0)

// ---------------------------------------------------------------------------
// Kernel 1: weight norms / exponents; resets fixup counter
// ---------------------------------------------------------------------------
__global__ void prep_w_kernel(const float* __restrict__ W,
                              const float* __restrict__ p,
                              const float* __restrict__ q) {
    __shared__ float red[256];
    int c = blockIdx.x, t = threadIdx.x;
    if (blockIdx.x == 0 && t == 0) g_fix_cnt = 0;
    float s = 0.0f;
    for (int k = t; k < KK; k += 256) {
        float w = W[k * Co + c];
        s = fmaf(w, w, s);
    }
    red[t] = s; __syncthreads();
    for (int o = 128; o > 0; o >>= 1) {
        if (t < o) red[t] += red[t + o];
        __syncthreads();
    }
    if (t == 0) {
        float qq = q[0] * q[0] * 0.1f;
        g_ws[c] = 1.0f / (sqrtf(red[0]) + qq);
        g_ae[c] = p[c] * p[c] * 0.01f;
    }
}

// ---------------------------------------------------------------------------
// Kernel 1b: weight transform G g G^T -> swizzled B image, plus g_WT fp32.
// blocks 0..127 = channel c; block 128 zeroes A-image pad rows (block 1512).
// ---------------------------------------------------------------------------
__global__ void wt_transform_kernel(const float* __restrict__ W) {
    if (blockIdx.x == 128) {
        // zero pad rows 16..31 of the last A m-block, every stage
        for (int i = threadIdx.x; i < 32 * 2048 / 16; i += 256) {
            int s = i / 128;            // stage
            int j = (i % 128) * 16;     // byte offset within pad region
            *reinterpret_cast<uint4*>(
                g_AtI + ((size_t)s * NMB + (NMB - 1)) * 4096 + 2048 + j) =
                make_uint4(0, 0, 0, 0);
        }
        return;
    }
    int c  = blockIdx.x;
    int co = threadIdx.x;
    float g[3][3];
    #pragma unroll
    for (int r = 0; r < 3; ++r)
        #pragma unroll
        for (int s = 0; s < 3; ++s) {
            float w = W[((r * 3 + s) * Cc + c) * Co + co];
            g[r][s] = w;
            g_WT[(size_t)co * KK + (r * 3 + s) * Cc + c] = w;
        }
    float u[4][3];
    #pragma unroll
    for (int s = 0; s < 3; ++s) {
        u[0][s] = g[0][s];
        u[1][s] = 0.5f * (g[0][s] + g[1][s] + g[2][s]);
        u[2][s] = 0.5f * (g[0][s] - g[1][s] + g[2][s]);
        u[3][s] = g[2][s];
    }
    int half = c >> 6;
    int ch   = (c & 63) >> 3;
    int e    = c & 7;
    uint32_t off = (uint32_t)co * 128u + (uint32_t)((ch ^ (co & 7)) << 4) + e * 2;
    #pragma unroll
    for (int i = 0; i < 4; ++i) {
        float v[4];
        v[0] = u[i][0];
        v[1] = 0.5f * (u[i][0] + u[i][1] + u[i][2]);
        v[2] = 0.5f * (u[i][0] - u[i][1] + u[i][2]);
        v[3] = u[i][2];
        #pragma unroll
        for (int j = 0; j < 4; ++j) {
            int st = (i * 4 + j) * 2 + half;
            *reinterpret_cast<__half*>(g_BtI + (size_t)st * 32768 + off) =
                __float2half_rn(v[j]);
        }
    }
}

// ---------------------------------------------------------------------------
// Kernel 2: per-input-pixel sum of x^2 (one warp per pixel)
// ---------------------------------------------------------------------------
__global__ void sumsq_kernel(const float* __restrict__ x) {
    int pix  = blockIdx.x * 8 + (threadIdx.x >> 5);
    int lane = threadIdx.x & 31;
    const float4* xp = reinterpret_cast<const float4*>(x + (size_t)pix * Cc);
    float4 v = xp[lane];
    float s = v.x * v.x + v.y * v.y + v.z * v.z + v.w * v.w;
    #pragma unroll
    for (int o = 16; o > 0; o >>= 1) s += __shfl_xor_sync(0xffffffffu, s, o);
    if (lane == 0) g_s[pix] = s;
}

// ---------------------------------------------------------------------------
// Kernel 3: 3x3 window sum -> inverse patch norm
// ---------------------------------------------------------------------------
__global__ void xnorm_kernel(const float* __restrict__ q) {
    int idx = blockIdx.x * 256 + threadIdx.x;
    if (idx >= MM) return;
    int n = idx / (Ho * Wo);
    int r = idx % (Ho * Wo);
    int h = r / Wo;
    int w = r % Wo;
    const float* sp = g_s + ((size_t)n * Hh + h) * Wd + w;
    float sum = 0.0f;
    #pragma unroll
    for (int ky = 0; ky < 3; ++ky)
        sum += sp[ky * Wd] + sp[ky * Wd + 1] + sp[ky * Wd + 2];
    float qq = q[0] * q[0] * 0.1f;
    g_xni[idx] = 1.0f / (sqrtf(sum) + qq);
}

// ---------------------------------------------------------------------------
// Kernel 4: input transform B^T d B -> swizzled A image.
// ---------------------------------------------------------------------------
__global__ void in_transform_kernel(const float* __restrict__ x) {
    int idx = blockIdx.x * 256 + threadIdx.x;    // TT*128 exact
    int t = idx >> 7;
    int c = idx & 127;
    int n  = t / THW;
    int rr = t % THW;
    int ty = rr / 55;
    int tx = rr % 55;
    const float* xp = x + (((size_t)n * Hh + 2 * ty) * Wd + 2 * tx) * Cc + c;

    float d[4][4];
    #pragma unroll
    for (int r = 0; r < 4; ++r)
        #pragma unroll
        for (int s = 0; s < 4; ++s)
            d[r][s] = xp[(r * Wd + s) * Cc];

    float u[4][4];
    #pragma unroll
    for (int s = 0; s < 4; ++s) {
        u[0][s] = d[0][s] - d[2][s];
        u[1][s] = d[1][s] + d[2][s];
        u[2][s] = d[2][s] - d[1][s];
        u[3][s] = d[1][s] - d[3][s];
    }
    int blk  = t >> 5;
    int row  = t & 31;
    int half = c >> 6;
    int ch   = (c & 63) >> 3;
    int e    = c & 7;
    uint32_t off = (uint32_t)row * 128u + (uint32_t)((ch ^ (row & 7)) << 4) + e * 2;
    #pragma unroll
    for (int i = 0; i < 4; ++i) {
        float v[4];
        v[0] = u[i][0] - u[i][2];
        v[1] = u[i][1] + u[i][2];
        v[2] = u[i][2] - u[i][1];
        v[3] = u[i][1] - u[i][3];
        #pragma unroll
        for (int j = 0; j < 4; ++j) {
            int st = (i * 4 + j) * 2 + half;
            *reinterpret_cast<__half*>(
                g_AtI + ((size_t)st * NMB + blk) * 4096 + off) =
                __float2half_rn(v[j]);
        }
    }
}

// ---------------------------------------------------------------------------
// Kernel 5: Winograd GEMM with bulk-copy staging. CTA = 32 tiles x 256 cout,
// 512 threads (16 warps, each 32t x 16co). 32 stages (ij x half), each staged
// by TWO cp.async.bulk ops (A 4KB + B 32KB) into a 3-deep ring.
// ---------------------------------------------------------------------------
#define NSTG 32
#define RG_B 4096
#define STG  36864              // A 4KB + B 32KB
#define SMEM_DYN (3 * STG)      // 110592
#define LISTCAP 8192

extern __shared__ char dsm[];

__global__ void __launch_bounds__(512, 1)
conv_wino_kernel(const float* __restrict__ bias, float* __restrict__ out) {
    __shared__ float s_ws[Co], s_ae[Co], s_bi[Co];
    __shared__ uint32_t s_cnt, s_base;
    __shared__ __align__(8) uint64_t s_mb[3];

    const uint32_t sbase = smem_u32(dsm);
    const uint32_t mbase = smem_u32(s_mb);
    const int t    = threadIdx.x;
    const int w    = t >> 5;
    const int lane = t & 31;
    const int gid  = lane >> 2;
    const int tig  = lane & 3;
    const int b    = blockIdx.x;
    const int t0   = b * 32;
    const int wno  = w * 16;

    if (t < Co) {
        s_ws[t] = g_ws[t];
        s_ae[t] = g_ae[t];
        s_bi[t] = bias[t];
    }
    if (t == 0) {
        s_cnt = 0;
        MBARRIER_INIT(mbase + 0,  1);
        MBARRIER_INIT(mbase + 8,  1);
        MBARRIER_INIT(mbase + 16, 1);
        FENCE_ASYNC();
    }
    __syncthreads();

    // ldmatrix invariants (verified in R7)
    const uint32_t sw    = lane & 7;
    const uint32_t aRow0 = (uint32_t)(lane & 15) * 128u;
    const uint32_t aRow1 = aRow0 + 16u * 128u;
    const uint32_t aCsel = (lane >> 4);
    const uint32_t bRow  = (uint32_t)(wno + ((lane >> 4) << 3) + (lane & 7)) * 128u;
    const uint32_t bCsel = (lane >> 3) & 1;

    float O0[16], O1[16], O2[16], O3[16], G[16];
    #pragma unroll
    for (int i = 0; i < 16; ++i) { O0[i]=0.f; O1[i]=0.f; O2[i]=0.f; O3[i]=0.f; G[i]=0.f; }

    #define ISSUE(s) do {                                                     \
        uint32_t buf = sbase + (uint32_t)((s) % 3) * STG;                     \
        uint32_t mb  = mbase + ((s) % 3) * 8;                                 \
        MBARRIER_EXPECT_TX(mb, STG);                                          \
        BULK_CP(buf, g_AtI + ((size_t)(s) * NMB + b) * 4096, 4096u, mb);      \
        BULK_CP(buf + RG_B, g_BtI + (size_t)(s) * 32768, 32768u, mb);         \
    } while (0)

    if (t == 0) { ISSUE(0); ISSUE(1); }

    for (int s = 0; s < NSTG; ++s) {
        if (t == 0 && s + 2 < NSTG) ISSUE(s + 2);
        MBARRIER_WAIT_PARITY(mbase + (s % 3) * 8, (s / 3) & 1);

        const uint32_t aB = sbase + (uint32_t)(s % 3) * STG;
        const uint32_t bB = aB + RG_B;

        #pragma unroll
        for (int ks = 0; ks < 4; ++ks) {
            const uint32_t offA = (((uint32_t)(2 * ks) + aCsel) ^ sw) << 4;
            const uint32_t offB = (((uint32_t)(2 * ks) + bCsel) ^ sw) << 4;
            uint32_t ah[2][4], bv[2][2];
            LDSM_X4(ah[0][0], ah[0][1], ah[0][2], ah[0][3], aB + aRow0 + offA);
            LDSM_X4(ah[1][0], ah[1][1], ah[1][2], ah[1][3], aB + aRow1 + offA);
            LDSM_X4(bv[0][0], bv[0][1], bv[1][0], bv[1][1], bB + bRow + offB);
            MMA_F16(G + 0,  ah[0], bv[0]);
            MMA_F16(G + 4,  ah[0], bv[1]);
            MMA_F16(G + 8,  ah[1], bv[0]);
            MMA_F16(G + 12, ah[1], bv[1]);
        }

        if (s & 1) {   // end of an ij phase: fold G into O with A^T coeffs
            int ij = s >> 1;
            int ii = ij >> 2, jj = ij & 3;
            float cy0 = c_a0[ii], cy1 = c_a1[ii];
            float cx0 = c_a0[jj], cx1 = c_a1[jj];
            float c00 = cy0 * cx0, c01 = cy0 * cx1;
            float c10 = cy1 * cx0, c11 = cy1 * cx1;
            #pragma unroll
            for (int r = 0; r < 16; ++r) {
                float gv = G[r];
                O0[r] = fmaf(c00, gv, O0[r]);
                O1[r] = fmaf(c01, gv, O1[r]);
                O2[r] = fmaf(c10, gv, O2[r]);
                O3[r] = fmaf(c11, gv, O3[r]);
                G[r] = 0.0f;
            }
        }
        __syncthreads();
    }

    // ---- fused epilogue: inverse-transformed accumulators -> 4 output pixels ----
    uint32_t* s_list = (uint32_t*)dsm;   // stage buffers dead

    #pragma unroll
    for (int mi = 0; mi < 2; ++mi) {
        #pragma unroll
        for (int e2 = 0; e2 < 2; ++e2) {
            int trow = t0 + mi * 16 + gid + 8 * e2;
            if (trow >= TT) continue;
            int n  = trow / THW;
            int rr = trow % THW;
            int ty = rr / 55;
            int tx = rr % 55;
            int mbaseo = n * (Ho * Wo) + 2 * ty * Wo + 2 * tx;
            #pragma unroll
            for (int y = 0; y < 2; ++y) {
                #pragma unroll
                for (int xx = 0; xx < 2; ++xx) {
                    int m = mbaseo + y * Wo + xx;
                    float xn = g_xni[m];
                    const float* Oa = (y == 0) ? (xx == 0 ? O0 : O1)
                                               : (xx == 0 ? O2 : O3);
                    #pragma unroll
                    for (int ni = 0; ni < 2; ++ni) {
                        int co = wno + ni * 8 + 2 * tig;
                        int ri = mi * 8 + ni * 4 + 2 * e2;
                        float f0 = Oa[ri]     + s_bi[co];
                        float f1 = Oa[ri + 1] + s_bi[co + 1];
                        float y0 = f0 * xn * s_ws[co];
                        float y1 = f1 * xn * s_ws[co + 1];
                        if (fabsf(y0) < TAU) {
                            uint32_t i = atomicAdd(&s_cnt, 1u);
                            if (i < LISTCAP) s_list[i] = ((uint32_t)m << 8) | (uint32_t)co;
                        }
                        if (fabsf(y1) < TAU) {
                            uint32_t i = atomicAdd(&s_cnt, 1u);
                            if (i < LISTCAP) s_list[i] = ((uint32_t)m << 8) | (uint32_t)(co + 1);
                        }
                        float a0 = fabsf(y0) + 1e-12f;
                        float a1 = fabsf(y1) + 1e-12f;
                        float o0 = copysignf(__expf(s_ae[co]     * __logf(a0)), f0);
                        float o1 = copysignf(__expf(s_ae[co + 1] * __logf(a1)), f1);
                        *reinterpret_cast<float2*>(out + (size_t)m * Co + co) =
                            make_float2(o0, o1);
                    }
                }
            }
        }
    }

    __syncthreads();
    if (t == 0) {
        uint32_t cc = s_cnt < LISTCAP ? s_cnt : LISTCAP;
        s_cnt = cc;
        s_base = atomicAdd(&g_fix_cnt, cc);
    }
    __syncthreads();
    for (uint32_t i = t; i < s_cnt; i += 512) {
        uint32_t gidx = s_base + i;
        if (gidx < FIXCAP) g_fix_list[gidx] = s_list[i];
    }
    #undef ISSUE
}

// ---------------------------------------------------------------------------
// Kernel 6: exact fp32 recompute of flagged elements (warp per candidate)
// ---------------------------------------------------------------------------
__global__ void fixup_kernel(const float* __restrict__ x,
                             const float* __restrict__ bias,
                             float* __restrict__ out) {
    uint32_t total = g_fix_cnt;
    if (total > FIXCAP) total = FIXCAP;
    uint32_t wid   = (blockIdx.x * blockDim.x + threadIdx.x) >> 5;
    uint32_t nwarp = (gridDim.x * blockDim.x) >> 5;
    int lane = threadIdx.x & 31;

    for (uint32_t e = wid; e < total; e += nwarp) {
        uint32_t enc = g_fix_list[e];
        int m  = enc >> 8;
        int co = enc & 255;
        int n = m / (Ho * Wo);
        int r = m % (Ho * Wo);
        int h = r / Wo;
        int ww = r % Wo;
        int base = ((n * Hh + h) * Wd + ww) * Cc;

        float sum = 0.0f;
        #pragma unroll
        for (int g = 0; g < 9; ++g) {
            int ky = g / 3, kx = g - ky * 3;
            const float* xp = x + base + (ky * Wd + kx) * Cc;
            const float* wp = g_WT + (size_t)co * KK + g * Cc;
            #pragma unroll
            for (int ci = 0; ci < 4; ++ci) {
                int cch = ci * 32 + lane;
                sum = fmaf(xp[cch], wp[cch], sum);
            }
        }
        #pragma unroll
        for (int o = 16; o > 0; o >>= 1)
            sum += __shfl_xor_sync(0xffffffffu, sum, o);

        if (lane == 0) {
            float f  = sum + bias[co];
            float y  = f * g_xni[m] * g_ws[co];
            float ay = fabsf(y) + 1e-12f;
            float rr = __expf(g_ae[co] * __logf(ay));
            out[(size_t)m * Co + co] = copysignf(rr, f);
        }
    }
}

// ---------------------------------------------------------------------------
extern "C" void kernel_launch(void* const* d_in, const int* in_sizes, int n_in,
                              void* d_out, int out_size) {
    const float* x = (const float*)d_in[0];
    const float* W = (const float*)d_in[1];
    const float* b = (const float*)d_in[2];
    const float* p = (const float*)d_in[3];
    const float* q = (const float*)d_in[4];
    float* out = (float*)d_out;

    prep_w_kernel<<<Co, 256>>>(W, p, q);
    wt_transform_kernel<<<129, 256>>>(W);
    sumsq_kernel<<<PIX / 8, 256>>>(x);
    xnorm_kernel<<<(MM + 255) / 256, 256>>>(q);
    in_transform_kernel<<<(TT * 128) / 256, 256>>>(x);

    static bool attr_set = false;
    if (!attr_set) {
        cudaFuncSetAttribute(conv_wino_kernel,
                             cudaFuncAttributeMaxDynamicSharedMemorySize, SMEM_DYN);
        attr_set = true;
    }
    conv_wino_kernel<<<NMB, 512, SMEM_DYN>>>(b, out);

    fixup_kernel<<<512, 256>>>(x, b, out);
}